// round 14
// baseline (speedup 1.0000x reference)
#include <cuda_runtime.h>
#include <cuda_fp16.h>
#include <mma.h>
#include <cstdint>

using namespace nvcuda;

#define N_B    4
#define S_LEN  2048
#define EMB    1024
#define HEADS  16
#define HD     64
#define MWORDS (S_LEN / 32)

#define PT   72    // fp16 smem pitch (144 B rows)
#define PSCR 20

// ---------------- scratch (device globals) ---------------------------------
__device__ __half g_q[N_B * HEADS * S_LEN * HD];    // single fp16, pre-scaled 1/32
__device__ __half g_k[N_B * HEADS * S_LEN * HD];
__device__ __half g_v[N_B * HEADS * S_LEN * HD];
__device__ __half g_ao[N_B * S_LEN * EMB];
__device__ __half g_wo[EMB * EMB];                  // single fp16
__device__ unsigned g_mbits[N_B * S_LEN * MWORDS];

__device__ __forceinline__ uint32_t pack2h(float a, float b) {
    __half2 h = __floats2half2_rn(a, b);
    return *reinterpret_cast<uint32_t*>(&h);
}

__device__ __forceinline__ uint32_t smem_u32(const void* p) {
    uint32_t a;
    asm("{ .reg .u64 t; cvta.to.shared.u64 t, %1; cvt.u32.u64 %0, t; }"
        : "=r"(a) : "l"(p));
    return a;
}

// ---- tensor-core / async-copy primitives ----------------------------------
__device__ __forceinline__ void ldsm_x4(uint32_t* r, uint32_t addr) {
    asm volatile("ldmatrix.sync.aligned.m8n8.x4.shared.b16 {%0,%1,%2,%3}, [%4];"
                 : "=r"(r[0]), "=r"(r[1]), "=r"(r[2]), "=r"(r[3]) : "r"(addr));
}
__device__ __forceinline__ void ldsm_x4_t(uint32_t* r, uint32_t addr) {
    asm volatile("ldmatrix.sync.aligned.m8n8.x4.trans.shared.b16 {%0,%1,%2,%3}, [%4];"
                 : "=r"(r[0]), "=r"(r[1]), "=r"(r[2]), "=r"(r[3]) : "r"(addr));
}
__device__ __forceinline__ void mma16816(float* d, const uint32_t* a, const uint32_t* b) {
    asm volatile(
        "mma.sync.aligned.m16n8k16.row.col.f32.f16.f16.f32 "
        "{%0,%1,%2,%3}, {%4,%5,%6,%7}, {%8,%9}, {%0,%1,%2,%3};"
        : "+f"(d[0]), "+f"(d[1]), "+f"(d[2]), "+f"(d[3])
        : "r"(a[0]), "r"(a[1]), "r"(a[2]), "r"(a[3]), "r"(b[0]), "r"(b[1]));
}
__device__ __forceinline__ void cp16(uint32_t dst, const void* src) {
    asm volatile("cp.async.cg.shared.global [%0], [%1], 16;" :: "r"(dst), "l"(src));
}
#define CP_COMMIT() asm volatile("cp.async.commit_group;" ::: "memory")
#define CP_WAIT0()  asm volatile("cp.async.wait_group 0;" ::: "memory")

// stage nrows x 64 f32 -> SINGLE fp16 smem pitch PT
__device__ __forceinline__ void stage_rows_f32_single(const float* __restrict__ src,
                                                      size_t stride, char* s_x, int t)
{
    const int r    = t >> 1;
    const int half = t & 1;
    const float4* s4 = (const float4*)(src + (size_t)r * stride) + half * 8;
#pragma unroll
    for (int tt = 0; tt < 4; tt++) {
        float4 a = s4[2 * tt], b = s4[2 * tt + 1];
        uint32_t H[4];
        H[0] = pack2h(a.x, a.y); H[1] = pack2h(a.z, a.w);
        H[2] = pack2h(b.x, b.y); H[3] = pack2h(b.z, b.w);
        uint32_t off = (uint32_t)(r * (PT * 2) + half * 64 + tt * 16);
        *(uint4*)(s_x + off) = make_uint4(H[0], H[1], H[2], H[3]);
    }
}

// ---------------------------------------------------------------------------
// Kernel 0a: pack mask bits
// ---------------------------------------------------------------------------
__global__ __launch_bounds__(256)
void mask_pack_kernel(const int* __restrict__ mask)
{
    int gid  = blockIdx.x * 256 + threadIdx.x;
    int w    = gid >> 5;
    int lane = gid & 31;
    int v = mask[(size_t)w * 32 + lane];
    unsigned bits = __ballot_sync(0xffffffffu, v != 0);
    if (lane == 0) g_mbits[w] = bits;
}

// ---------------------------------------------------------------------------
// Kernel 0b: convert Wo to single fp16
// ---------------------------------------------------------------------------
__global__ __launch_bounds__(256)
void wo_half_kernel(const float* __restrict__ Wo)
{
    size_t idx = ((size_t)blockIdx.x * 256 + threadIdx.x) * 8;
    float4 a = *(const float4*)(Wo + idx);
    float4 b = *(const float4*)(Wo + idx + 4);
    uint32_t H[4];
    H[0] = pack2h(a.x, a.y); H[1] = pack2h(a.z, a.w);
    H[2] = pack2h(b.x, b.y); H[3] = pack2h(b.z, b.w);
    *(uint4*)(g_wo + idx) = make_uint4(H[0], H[1], H[2], H[3]);
}

// ---------------------------------------------------------------------------
// Kernel 1: projections — X and W single fp16 (1 MMA per step); Q scaled 1/32
// ---------------------------------------------------------------------------
#define PJ_W   0
#define PJ_X   9216
#define PJ_SCR 27648
#define PJ_SMEM (27648 + 10240)

__global__ __launch_bounds__(256, 2)
void proj_wmma_kernel(const float* __restrict__ xq, const float* __restrict__ xk,
                      const float* __restrict__ xv,
                      const float* __restrict__ Wq, const float* __restrict__ Wk,
                      const float* __restrict__ Wv)
{
    extern __shared__ char sm[];
    __half* Ws = (__half*)(sm + PJ_W);
    __half* Xs = (__half*)(sm + PJ_X);

    const int which = blockIdx.z;
    const float* X; const float* W; __half* Y;
    if (which == 0)      { X = xq; W = Wq; Y = g_q; }
    else if (which == 1) { X = xk; W = Wk; Y = g_k; }
    else                 { X = xv; W = Wv; Y = g_v; }
    const float oscale = (which == 0) ? 0.03125f : 1.0f;

    const int nh = blockIdx.y;
    const int n  = nh / HEADS;
    const int h  = nh % HEADS;
    const int s0 = blockIdx.x * 128;
    const int tid = threadIdx.x, wid = tid >> 5, lane = tid & 31;
    float* scr = (float*)(sm + PJ_SCR) + wid * (16 * PSCR);

    stage_rows_f32_single(X + (size_t)(n * S_LEN + s0) * EMB + h * HD, EMB,
                          (char*)Xs, tid);
    if (tid < 128)
        stage_rows_f32_single(W, HD, (char*)Ws, tid);
    __syncthreads();

    wmma::fragment<wmma::accumulator, 16, 16, 16, float> acc[4];
#pragma unroll
    for (int j = 0; j < 4; j++) wmma::fill_fragment(acc[j], 0.0f);

#pragma unroll
    for (int kk = 0; kk < 4; kk++) {
        wmma::fragment<wmma::matrix_a, 16, 16, 16, __half, wmma::row_major> ax;
        wmma::load_matrix_sync(ax, Xs + wid * 16 * PT + kk * 16, PT);
#pragma unroll
        for (int j = 0; j < 4; j++) {
            wmma::fragment<wmma::matrix_b, 16, 16, 16, __half, wmma::col_major> bw;
            wmma::load_matrix_sync(bw, Ws + j * 16 * PT + kk * 16, PT);
            wmma::mma_sync(acc[j], ax, bw, acc[j]);
        }
    }

    const int r = lane >> 1, cw = lane & 1;
    const size_t ybase = (size_t)((n * HEADS + h) * S_LEN + s0 + wid * 16) * HD;
#pragma unroll
    for (int j = 0; j < 4; j++) {
        wmma::store_matrix_sync(scr, acc[j], PSCR, wmma::mem_row_major);
        __syncwarp();
        const float* s = scr + r * PSCR + cw * 8;
        uint32_t H[4];
#pragma unroll
        for (int u = 0; u < 4; u++)
            H[u] = pack2h(s[2 * u] * oscale, s[2 * u + 1] * oscale);
        *(uint4*)(Y + ybase + (size_t)r * HD + j * 16 + cw * 8) =
            make_uint4(H[0], H[1], H[2], H[3]);
        __syncwarp();
    }
}

// ---------------------------------------------------------------------------
// Kernel 2: flash attention — q-tile 256, 32 q-rows per warp (B-frag reuse 2x)
// grid (HEADS, S_LEN/256, N_B), 256 threads, kv-tile 32, 2-stage cp.async
// smem: Q 36864 + 2 KV stages of 9216 (K 0 / V 4608)
// ---------------------------------------------------------------------------
#define A_Q    0
#define A_KV0  36864
#define A_KV1  46080
#define KV_V   4608
#define ATTN_SMEM (55296 + 256)
#define NIT (S_LEN / 32)

__global__ __launch_bounds__(256, 1)
void attn_mma_kernel()
{
    extern __shared__ char sm[];
    const int tid = threadIdx.x, wid = tid >> 5, lane = tid & 31;
    const int h = blockIdx.x, qt = blockIdx.y, n = blockIdx.z;
    const int q0 = qt * 256;

    const size_t head_base = (size_t)(n * HEADS + h) * S_LEN * HD;
    const __half* Q = g_q + head_base + (size_t)q0 * HD;
    const __half* K = g_k + head_base;
    const __half* V = g_v + head_base;

    const uint32_t smb = smem_u32(sm);

    // ---- prefetch KV tile 0 ----
    const int str = tid >> 3, soct = tid & 7;
    const uint32_t soff = (uint32_t)(str * (PT * 2) + soct * 16);
    {
        const size_t gsrc = (size_t)str * HD + soct * 8;
        cp16(smb + A_KV0 + soff,        K + gsrc);
        cp16(smb + A_KV0 + KV_V + soff, V + gsrc);
    }
    CP_COMMIT();

    // ---- stage Q (256 rows, one row per thread) ----
    {
        const char* sq = (const char*)(Q + (size_t)tid * HD);
        uint32_t off = (uint32_t)(tid * (PT * 2));
#pragma unroll
        for (int tt = 0; tt < 8; tt++)
            *(uint4*)(sm + A_Q + off + tt * 16) = *(const uint4*)(sq + tt * 16);
    }
    __syncthreads();

    const int l7  = lane & 7;
    const int s01 = (lane >> 3) & 1;
    const int s23 = (lane >> 4) & 1;

    // two A-fragment sets: rows wid*32+[0,16) and +[16,32)
    uint32_t qa[4][4], qb[4][4];
    {
        uint32_t base = smb + (uint32_t)((wid * 32 + l7 + s01 * 8) * (PT * 2)) + s23 * 16;
#pragma unroll
        for (int c = 0; c < 4; c++) {
            ldsm_x4(qa[c], base + A_Q + c * 32);
            ldsm_x4(qb[c], base + A_Q + 16 * (PT * 2) + c * 32);
        }
    }

    const int g   = lane >> 2;
    const int tig = lane & 3;
    const int qrow_g = q0 + wid * 32 + g;
    const unsigned* mr0  = g_mbits + (size_t)(n * S_LEN + qrow_g) * MWORDS;
    const unsigned* mr8  = mr0 + 8  * MWORDS;
    const unsigned* mr16 = mr0 + 16 * MWORDS;
    const unsigned* mr24 = mr0 + 24 * MWORDS;

    const uint32_t kqoff = (uint32_t)(((lane >> 4) * 8 + l7) * (PT * 2)) + ((lane >> 3) & 1) * 16;
    const uint32_t voff  = (uint32_t)((((lane >> 3) & 1) * 8 + l7) * (PT * 2)) + (lane >> 4) * 16;

    float oa[8][4], ob[8][4];
#pragma unroll
    for (int j = 0; j < 8; j++)
#pragma unroll
        for (int u = 0; u < 4; u++) { oa[j][u] = 0.f; ob[j][u] = 0.f; }
    float ls0 = 0.f, ls8 = 0.f, ls16 = 0.f, ls24 = 0.f;

    for (int it = 0; it < NIT; it++) {
        const uint32_t kv = smb + ((it & 1) ? A_KV1 : A_KV0);

        CP_WAIT0();
        __syncthreads();

        if (it + 1 < NIT) {
            const size_t gsrc = (size_t)((it + 1) * 32 + str) * HD + soct * 8;
            const uint32_t d = smb + (((it + 1) & 1) ? A_KV1 : A_KV0);
            cp16(d + soff,        K + gsrc);
            cp16(d + KV_V + soff, V + gsrc);
        }
        CP_COMMIT();

        // ---- S = Q K^T for both 16-row halves (K frags loaded once) ----
        float sa[4][4], sb[4][4];
#pragma unroll
        for (int j = 0; j < 4; j++)
#pragma unroll
            for (int u = 0; u < 4; u++) { sa[j][u] = 0.f; sb[j][u] = 0.f; }

#pragma unroll
        for (int c = 0; c < 4; c++) {
            uint32_t bh0[4], bh1[4];
            const uint32_t ka0 = kv + kqoff + c * 32;
            const uint32_t ka1 = ka0 + (uint32_t)(16 * (PT * 2));
            ldsm_x4(bh0, ka0);
            ldsm_x4(bh1, ka1);
            mma16816(sa[0], qa[c], bh0); mma16816(sa[1], qa[c], bh0 + 2);
            mma16816(sa[2], qa[c], bh1); mma16816(sa[3], qa[c], bh1 + 2);
            mma16816(sb[0], qb[c], bh0); mma16816(sb[1], qb[c], bh0 + 2);
            mma16816(sb[2], qb[c], bh1); mma16816(sb[3], qb[c], bh1 + 2);
        }

        // ---- softmax in registers ----
        const unsigned w0  = mr0[it];
        const unsigned w8  = mr8[it];
        const unsigned w16 = mr16[it];
        const unsigned w24 = mr24[it];
#pragma unroll
        for (int j = 0; j < 4; j++) {
            const int bit = j * 8 + tig * 2;
            float p0 = __expf(sa[j][0]);
            float p1 = __expf(sa[j][1]);
            float p2 = __expf(sa[j][2]);
            float p3 = __expf(sa[j][3]);
            p0 = ((w0 >> bit) & 1u)       ? p0 : 0.f;
            p1 = ((w0 >> (bit + 1)) & 1u) ? p1 : 0.f;
            p2 = ((w8 >> bit) & 1u)       ? p2 : 0.f;
            p3 = ((w8 >> (bit + 1)) & 1u) ? p3 : 0.f;
            ls0 += p0 + p1; ls8 += p2 + p3;
            sa[j][0] = p0; sa[j][1] = p1; sa[j][2] = p2; sa[j][3] = p3;

            float r0 = __expf(sb[j][0]);
            float r1 = __expf(sb[j][1]);
            float r2 = __expf(sb[j][2]);
            float r3 = __expf(sb[j][3]);
            r0 = ((w16 >> bit) & 1u)       ? r0 : 0.f;
            r1 = ((w16 >> (bit + 1)) & 1u) ? r1 : 0.f;
            r2 = ((w24 >> bit) & 1u)       ? r2 : 0.f;
            r3 = ((w24 >> (bit + 1)) & 1u) ? r3 : 0.f;
            ls16 += r0 + r1; ls24 += r2 + r3;
            sb[j][0] = r0; sb[j][1] = r1; sb[j][2] = r2; sb[j][3] = r3;
        }

        // ---- O += P V (V frags loaded once, used by both halves) ----
#pragma unroll
        for (int c2 = 0; c2 < 2; c2++) {
            uint32_t aha[4], ahb[4];
            aha[0] = pack2h(sa[2 * c2][0],     sa[2 * c2][1]);
            aha[1] = pack2h(sa[2 * c2][2],     sa[2 * c2][3]);
            aha[2] = pack2h(sa[2 * c2 + 1][0], sa[2 * c2 + 1][1]);
            aha[3] = pack2h(sa[2 * c2 + 1][2], sa[2 * c2 + 1][3]);
            ahb[0] = pack2h(sb[2 * c2][0],     sb[2 * c2][1]);
            ahb[1] = pack2h(sb[2 * c2][2],     sb[2 * c2][3]);
            ahb[2] = pack2h(sb[2 * c2 + 1][0], sb[2 * c2 + 1][1]);
            ahb[3] = pack2h(sb[2 * c2 + 1][2], sb[2 * c2 + 1][3]);
#pragma unroll
            for (int jp = 0; jp < 4; jp++) {
                uint32_t bh[4];
                const uint32_t va = kv + KV_V + voff +
                                    (uint32_t)(c2 * 16 * (PT * 2)) + jp * 32;
                ldsm_x4_t(bh, va);
                mma16816(oa[2 * jp],     aha, bh);
                mma16816(oa[2 * jp + 1], aha, bh + 2);
                mma16816(ob[2 * jp],     ahb, bh);
                mma16816(ob[2 * jp + 1], ahb, bh + 2);
            }
        }
    }

    // ---- epilogue ----
    ls0  += __shfl_xor_sync(0xffffffffu, ls0, 1);
    ls0  += __shfl_xor_sync(0xffffffffu, ls0, 2);
    ls8  += __shfl_xor_sync(0xffffffffu, ls8, 1);
    ls8  += __shfl_xor_sync(0xffffffffu, ls8, 2);
    ls16 += __shfl_xor_sync(0xffffffffu, ls16, 1);
    ls16 += __shfl_xor_sync(0xffffffffu, ls16, 2);
    ls24 += __shfl_xor_sync(0xffffffffu, ls24, 1);
    ls24 += __shfl_xor_sync(0xffffffffu, ls24, 2);
    const float i0  = 1.0f / ls0;
    const float i8  = 1.0f / ls8;
    const float i16 = 1.0f / ls16;
    const float i24 = 1.0f / ls24;

    const size_t d0  = (size_t)(n * S_LEN + qrow_g) * EMB + h * HD;
    const size_t d8  = d0 + (size_t)8  * EMB;
    const size_t d16 = d0 + (size_t)16 * EMB;
    const size_t d24 = d0 + (size_t)24 * EMB;
#pragma unroll
    for (int j = 0; j < 8; j++) {
        const int col = j * 8 + tig * 2;
        *(uint32_t*)(g_ao + d0  + col) = pack2h(oa[j][0] * i0,  oa[j][1] * i0);
        *(uint32_t*)(g_ao + d8  + col) = pack2h(oa[j][2] * i8,  oa[j][3] * i8);
        *(uint32_t*)(g_ao + d16 + col) = pack2h(ob[j][0] * i16, ob[j][1] * i16);
        *(uint32_t*)(g_ao + d24 + col) = pack2h(ob[j][2] * i24, ob[j][3] * i24);
    }
}

// ---------------------------------------------------------------------------
// Kernel 3: output projection — A and Wo single fp16, BK=32, 2-stage ring
// (unchanged from R13)
// ---------------------------------------------------------------------------
#define OPKB    80
#define OB2_SZ  20480
#define OB2_B   10240
#define OUT2_SMEM (2 * 20480 + 128)
#define ONIT2 (EMB / 32)

__global__ __launch_bounds__(256, 2)
void out_mma_kernel(const float* __restrict__ bo, float* __restrict__ out)
{
    extern __shared__ char sm[];
    const uint32_t smb = smem_u32(sm);

    const int tid = threadIdx.x, wid = tid >> 5, lane = tid & 31;
    const int r0 = blockIdx.y * 128;
    const int e0 = blockIdx.x * 128;
    const int wr = wid & 3;
    const int wc = wid >> 2;

    const int l7  = lane & 7;
    const int s01 = (lane >> 3) & 1;
    const int s23 = lane >> 4;
    const uint32_t aoff = (uint32_t)((l7 + s01 * 8) * OPKB) + s23 * 16;
    const uint32_t boff = (uint32_t)((s23 * 8 + l7) * OPKB) + s01 * 16;

    float acc[2][8][4];
#pragma unroll
    for (int m = 0; m < 2; m++)
#pragma unroll
        for (int j = 0; j < 8; j++)
#pragma unroll
            for (int u = 0; u < 4; u++) acc[m][j][u] = 0.f;

    const int ar0 = tid >> 2,          aq0 = tid & 3;
    const int ar1 = (tid + 256) >> 2,  aq1 = tid & 3;
    const uint32_t os0 = (uint32_t)(ar0 * OPKB + aq0 * 16);
    const uint32_t os1 = (uint32_t)(ar1 * OPKB + aq1 * 16);
    const size_t ag0 = (size_t)(r0 + ar0) * EMB + aq0 * 8;
    const size_t ag1 = (size_t)(r0 + ar1) * EMB + aq1 * 8;
    const size_t bg0 = (size_t)(e0 + ar0) * EMB + aq0 * 8;
    const size_t bg1 = (size_t)(e0 + ar1) * EMB + aq1 * 8;

    {
        const uint32_t d = smb;
        cp16(d + os0,         g_ao + ag0);  cp16(d + os1,         g_ao + ag1);
        cp16(d + OB2_B + os0, g_wo + bg0);  cp16(d + OB2_B + os1, g_wo + bg1);
    }
    CP_COMMIT();

    for (int ic = 0; ic < ONIT2; ic++) {
        const uint32_t buf = smb + (ic & 1) * OB2_SZ;

        CP_WAIT0();
        __syncthreads();

        if (ic + 1 < ONIT2) {
            const int c1 = (ic + 1) * 32;
            const uint32_t d = smb + ((ic + 1) & 1) * OB2_SZ;
            cp16(d + os0,         g_ao + ag0 + c1);  cp16(d + os1,         g_ao + ag1 + c1);
            cp16(d + OB2_B + os0, g_wo + bg0 + c1);  cp16(d + OB2_B + os1, g_wo + bg1 + c1);
        }
        CP_COMMIT();

#pragma unroll
        for (int kk = 0; kk < 2; kk++) {
            uint32_t ah0[4], ah1[4];
            const uint32_t aa0 = buf + (uint32_t)(wr * 32 * OPKB) + aoff + kk * 32;
            const uint32_t aa1 = aa0 + (uint32_t)(16 * OPKB);
            ldsm_x4(ah0, aa0);
            ldsm_x4(ah1, aa1);
#pragma unroll
            for (int jj = 0; jj < 4; jj++) {
                uint32_t bh[4];
                const uint32_t ba = buf + OB2_B +
                    (uint32_t)((wc * 64 + jj * 16) * OPKB) + boff + kk * 32;
                ldsm_x4(bh, ba);
                mma16816(acc[0][2 * jj],     ah0, bh); mma16816(acc[0][2 * jj + 1], ah0, bh + 2);
                mma16816(acc[1][2 * jj],     ah1, bh); mma16816(acc[1][2 * jj + 1], ah1, bh + 2);
            }
        }
    }

    const int g   = lane >> 2;
    const int tig = lane & 3;
#pragma unroll
    for (int m = 0; m < 2; m++) {
        const int row  = r0 + wr * 32 + m * 16 + g;
        const int row8 = row + 8;
#pragma unroll
        for (int jn = 0; jn < 8; jn++) {
            const int col = e0 + wc * 64 + jn * 8 + tig * 2;
            const float2 bb = *(const float2*)(bo + col);
            float2 v0 = make_float2(acc[m][jn][0] + bb.x, acc[m][jn][1] + bb.y);
            float2 v1 = make_float2(acc[m][jn][2] + bb.x, acc[m][jn][3] + bb.y);
            *(float2*)(out + (size_t)row  * EMB + col) = v0;
            *(float2*)(out + (size_t)row8 * EMB + col) = v1;
        }
    }
}

// ---------------------------------------------------------------------------
extern "C" void kernel_launch(void* const* d_in, const int* in_sizes, int n_in,
                              void* d_out, int out_size)
{
    const float* values  = (const float*)d_in[0];
    const float* queries = (const float*)d_in[1];
    const float* keys    = (const float*)d_in[2];
    const int*   mask    = (const int*)  d_in[3];
    const float* Wv      = (const float*)d_in[4];
    const float* Wk      = (const float*)d_in[5];
    const float* Wq      = (const float*)d_in[6];
    const float* Wo      = (const float*)d_in[7];
    const float* bo      = (const float*)d_in[8];
    float* out = (float*)d_out;

    static bool attr_set = false;
    if (!attr_set) {
        cudaFuncSetAttribute(proj_wmma_kernel,
                             cudaFuncAttributeMaxDynamicSharedMemorySize, PJ_SMEM);
        cudaFuncSetAttribute(attn_mma_kernel,
                             cudaFuncAttributeMaxDynamicSharedMemorySize, ATTN_SMEM);
        cudaFuncSetAttribute(out_mma_kernel,
                             cudaFuncAttributeMaxDynamicSharedMemorySize, OUT2_SMEM);
        attr_set = true;
    }

    mask_pack_kernel<<<(N_B * S_LEN * MWORDS * 32) / 256, 256>>>(mask);
    wo_half_kernel<<<(EMB * EMB) / (256 * 8), 256>>>(Wo);

    dim3 pgrid(S_LEN / 128, N_B * HEADS, 3);
    proj_wmma_kernel<<<pgrid, 256, PJ_SMEM>>>(queries, keys, values, Wq, Wk, Wv);

    dim3 agrid(HEADS, S_LEN / 256, N_B);
    attn_mma_kernel<<<agrid, 256, ATTN_SMEM>>>();

    dim3 ggrid(EMB / 128, (N_B * S_LEN) / 128);
    out_mma_kernel<<<ggrid, 256, OUT2_SMEM>>>(bo, out);
}

// round 15
// speedup vs baseline: 1.1851x; 1.1851x over previous
#include <cuda_runtime.h>
#include <cuda_fp16.h>
#include <mma.h>
#include <cstdint>

using namespace nvcuda;

#define N_B    4
#define S_LEN  2048
#define EMB    1024
#define HEADS  16
#define HD     64
#define MWORDS (S_LEN / 32)

#define PT   72    // fp16 smem pitch (144 B rows)
#define PSCR 20

// ---------------- scratch (device globals) ---------------------------------
__device__ __half g_q[N_B * HEADS * S_LEN * HD];    // fp16, pre-scaled log2(e)/32
__device__ __half g_k[N_B * HEADS * S_LEN * HD];
__device__ __half g_v[N_B * HEADS * S_LEN * HD];
__device__ __half g_ao[N_B * S_LEN * EMB];
__device__ __half g_wo[EMB * EMB];
__device__ unsigned g_mbits[N_B * S_LEN * MWORDS];

__device__ __forceinline__ uint32_t pack2h(float a, float b) {
    __half2 h = __floats2half2_rn(a, b);
    return *reinterpret_cast<uint32_t*>(&h);
}

__device__ __forceinline__ uint32_t smem_u32(const void* p) {
    uint32_t a;
    asm("{ .reg .u64 t; cvta.to.shared.u64 t, %1; cvt.u32.u64 %0, t; }"
        : "=r"(a) : "l"(p));
    return a;
}

// ---- tensor-core / async-copy primitives ----------------------------------
__device__ __forceinline__ void ldsm_x4(uint32_t* r, uint32_t addr) {
    asm volatile("ldmatrix.sync.aligned.m8n8.x4.shared.b16 {%0,%1,%2,%3}, [%4];"
                 : "=r"(r[0]), "=r"(r[1]), "=r"(r[2]), "=r"(r[3]) : "r"(addr));
}
__device__ __forceinline__ void ldsm_x4_t(uint32_t* r, uint32_t addr) {
    asm volatile("ldmatrix.sync.aligned.m8n8.x4.trans.shared.b16 {%0,%1,%2,%3}, [%4];"
                 : "=r"(r[0]), "=r"(r[1]), "=r"(r[2]), "=r"(r[3]) : "r"(addr));
}
__device__ __forceinline__ void mma16816(float* d, const uint32_t* a, const uint32_t* b) {
    asm volatile(
        "mma.sync.aligned.m16n8k16.row.col.f32.f16.f16.f32 "
        "{%0,%1,%2,%3}, {%4,%5,%6,%7}, {%8,%9}, {%0,%1,%2,%3};"
        : "+f"(d[0]), "+f"(d[1]), "+f"(d[2]), "+f"(d[3])
        : "r"(a[0]), "r"(a[1]), "r"(a[2]), "r"(a[3]), "r"(b[0]), "r"(b[1]));
}
__device__ __forceinline__ void cp16(uint32_t dst, const void* src) {
    asm volatile("cp.async.cg.shared.global [%0], [%1], 16;" :: "r"(dst), "l"(src));
}
#define CP_COMMIT() asm volatile("cp.async.commit_group;" ::: "memory")
#define CP_WAIT0()  asm volatile("cp.async.wait_group 0;" ::: "memory")

// stage nrows x 64 f32 -> SINGLE fp16 smem pitch PT
__device__ __forceinline__ void stage_rows_f32_single(const float* __restrict__ src,
                                                      size_t stride, char* s_x, int t)
{
    const int r    = t >> 1;
    const int half = t & 1;
    const float4* s4 = (const float4*)(src + (size_t)r * stride) + half * 8;
#pragma unroll
    for (int tt = 0; tt < 4; tt++) {
        float4 a = s4[2 * tt], b = s4[2 * tt + 1];
        uint32_t H[4];
        H[0] = pack2h(a.x, a.y); H[1] = pack2h(a.z, a.w);
        H[2] = pack2h(b.x, b.y); H[3] = pack2h(b.z, b.w);
        uint32_t off = (uint32_t)(r * (PT * 2) + half * 64 + tt * 16);
        *(uint4*)(s_x + off) = make_uint4(H[0], H[1], H[2], H[3]);
    }
}

// ---------------------------------------------------------------------------
// Kernel 0a: pack mask bits
// ---------------------------------------------------------------------------
__global__ __launch_bounds__(256)
void mask_pack_kernel(const int* __restrict__ mask)
{
    int gid  = blockIdx.x * 256 + threadIdx.x;
    int w    = gid >> 5;
    int lane = gid & 31;
    int v = mask[(size_t)w * 32 + lane];
    unsigned bits = __ballot_sync(0xffffffffu, v != 0);
    if (lane == 0) g_mbits[w] = bits;
}

// ---------------------------------------------------------------------------
// Kernel 0b: convert Wo to single fp16
// ---------------------------------------------------------------------------
__global__ __launch_bounds__(256)
void wo_half_kernel(const float* __restrict__ Wo)
{
    size_t idx = ((size_t)blockIdx.x * 256 + threadIdx.x) * 8;
    float4 a = *(const float4*)(Wo + idx);
    float4 b = *(const float4*)(Wo + idx + 4);
    uint32_t H[4];
    H[0] = pack2h(a.x, a.y); H[1] = pack2h(a.z, a.w);
    H[2] = pack2h(b.x, b.y); H[3] = pack2h(b.z, b.w);
    *(uint4*)(g_wo + idx) = make_uint4(H[0], H[1], H[2], H[3]);
}

// ---------------------------------------------------------------------------
// Kernel 1: projections — X and W single fp16; Q pre-scaled log2(e)/32
// ---------------------------------------------------------------------------
#define PJ_W   0
#define PJ_X   9216
#define PJ_SCR 27648
#define PJ_SMEM (27648 + 10240)

__global__ __launch_bounds__(256, 2)
void proj_wmma_kernel(const float* __restrict__ xq, const float* __restrict__ xk,
                      const float* __restrict__ xv,
                      const float* __restrict__ Wq, const float* __restrict__ Wk,
                      const float* __restrict__ Wv)
{
    extern __shared__ char sm[];
    __half* Ws = (__half*)(sm + PJ_W);
    __half* Xs = (__half*)(sm + PJ_X);

    const int which = blockIdx.z;
    const float* X; const float* W; __half* Y;
    if (which == 0)      { X = xq; W = Wq; Y = g_q; }
    else if (which == 1) { X = xk; W = Wk; Y = g_k; }
    else                 { X = xv; W = Wv; Y = g_v; }
    // Q scale: log2(e) / sqrt(EMB) so softmax can use exp2f directly
    const float oscale = (which == 0) ? (1.4426950408889634f * 0.03125f) : 1.0f;

    const int nh = blockIdx.y;
    const int n  = nh / HEADS;
    const int h  = nh % HEADS;
    const int s0 = blockIdx.x * 128;
    const int tid = threadIdx.x, wid = tid >> 5, lane = tid & 31;
    float* scr = (float*)(sm + PJ_SCR) + wid * (16 * PSCR);

    stage_rows_f32_single(X + (size_t)(n * S_LEN + s0) * EMB + h * HD, EMB,
                          (char*)Xs, tid);
    if (tid < 128)
        stage_rows_f32_single(W, HD, (char*)Ws, tid);
    __syncthreads();

    wmma::fragment<wmma::accumulator, 16, 16, 16, float> acc[4];
#pragma unroll
    for (int j = 0; j < 4; j++) wmma::fill_fragment(acc[j], 0.0f);

#pragma unroll
    for (int kk = 0; kk < 4; kk++) {
        wmma::fragment<wmma::matrix_a, 16, 16, 16, __half, wmma::row_major> ax;
        wmma::load_matrix_sync(ax, Xs + wid * 16 * PT + kk * 16, PT);
#pragma unroll
        for (int j = 0; j < 4; j++) {
            wmma::fragment<wmma::matrix_b, 16, 16, 16, __half, wmma::col_major> bw;
            wmma::load_matrix_sync(bw, Ws + j * 16 * PT + kk * 16, PT);
            wmma::mma_sync(acc[j], ax, bw, acc[j]);
        }
    }

    const int r = lane >> 1, cw = lane & 1;
    const size_t ybase = (size_t)((n * HEADS + h) * S_LEN + s0 + wid * 16) * HD;
#pragma unroll
    for (int j = 0; j < 4; j++) {
        wmma::store_matrix_sync(scr, acc[j], PSCR, wmma::mem_row_major);
        __syncwarp();
        const float* s = scr + r * PSCR + cw * 8;
        uint32_t H[4];
#pragma unroll
        for (int u = 0; u < 4; u++)
            H[u] = pack2h(s[2 * u] * oscale, s[2 * u + 1] * oscale);
        *(uint4*)(Y + ybase + (size_t)r * HD + j * 16 + cw * 8) =
            make_uint4(H[0], H[1], H[2], H[3]);
        __syncwarp();
    }
}

// ---------------------------------------------------------------------------
// Kernel 2: flash attention — R13 config (q-tile 128, 2 CTA/SM), exp2f softmax
// grid (HEADS, S_LEN/128, N_B), 256 threads, kv-tile 32, 2-stage cp.async
// ---------------------------------------------------------------------------
#define A_Q    0
#define A_KV0  18432
#define A_KV1  27648
#define KV_V   4608
#define ATTN_SMEM (36864 + 256)
#define NIT (S_LEN / 32)

__global__ __launch_bounds__(256, 2)
void attn_mma_kernel()
{
    extern __shared__ char sm[];
    const int tid = threadIdx.x, wid = tid >> 5, lane = tid & 31;
    const int h = blockIdx.x, qt = blockIdx.y, n = blockIdx.z;
    const int q0 = qt * 128;

    const size_t head_base = (size_t)(n * HEADS + h) * S_LEN * HD;
    const __half* Q = g_q + head_base + (size_t)q0 * HD;
    const __half* K = g_k + head_base;
    const __half* V = g_v + head_base;

    const uint32_t smb = smem_u32(sm);

    // ---- prefetch KV tile 0 ----
    const int str = tid >> 3, soct = tid & 7;
    const uint32_t soff = (uint32_t)(str * (PT * 2) + soct * 16);
    {
        const size_t gsrc = (size_t)str * HD + soct * 8;
        cp16(smb + A_KV0 + soff,        K + gsrc);
        cp16(smb + A_KV0 + KV_V + soff, V + gsrc);
    }
    CP_COMMIT();

    // ---- stage Q, hoist fragments ----
    {
        const int r = tid >> 1, half = tid & 1;
        const char* sq = (const char*)(Q + (size_t)r * HD + half * 32);
        uint32_t off = (uint32_t)(r * (PT * 2) + half * 64);
#pragma unroll
        for (int tt = 0; tt < 4; tt++)
            *(uint4*)(sm + A_Q + off + tt * 16) = *(const uint4*)(sq + tt * 16);
    }
    __syncthreads();

    const int l7  = lane & 7;
    const int s01 = (lane >> 3) & 1;
    const int s23 = (lane >> 4) & 1;

    uint32_t qh[4][4];
    {
        uint32_t base = smb + (uint32_t)((wid * 16 + l7 + s01 * 8) * (PT * 2)) + s23 * 16;
#pragma unroll
        for (int c = 0; c < 4; c++)
            ldsm_x4(qh[c], base + A_Q + c * 32);
    }

    const int g   = lane >> 2;
    const int tig = lane & 3;
    const int qrow_g  = q0 + wid * 16 + g;
    const unsigned* mrow0 = g_mbits + (size_t)(n * S_LEN + qrow_g) * MWORDS;
    const unsigned* mrow8 = mrow0 + 8 * MWORDS;

    const uint32_t kqoff = (uint32_t)(((lane >> 4) * 8 + l7) * (PT * 2)) + ((lane >> 3) & 1) * 16;
    const uint32_t voff  = (uint32_t)((((lane >> 3) & 1) * 8 + l7) * (PT * 2)) + (lane >> 4) * 16;

    float o[8][4];
#pragma unroll
    for (int j = 0; j < 8; j++)
#pragma unroll
        for (int u = 0; u < 4; u++) o[j][u] = 0.f;
    float lsum_g = 0.f, lsum_8 = 0.f;

    for (int it = 0; it < NIT; it++) {
        const uint32_t kv = smb + ((it & 1) ? A_KV1 : A_KV0);

        CP_WAIT0();
        __syncthreads();

        if (it + 1 < NIT) {
            const size_t gsrc = (size_t)((it + 1) * 32 + str) * HD + soct * 8;
            const uint32_t d = smb + (((it + 1) & 1) ? A_KV1 : A_KV0);
            cp16(d + soff,        K + gsrc);
            cp16(d + KV_V + soff, V + gsrc);
        }
        CP_COMMIT();

        // ---- S = Q K^T (Q pre-scaled by log2e/32) ----
        float s[4][4];
#pragma unroll
        for (int j = 0; j < 4; j++)
#pragma unroll
            for (int u = 0; u < 4; u++) s[j][u] = 0.f;

#pragma unroll
        for (int c = 0; c < 4; c++) {
            uint32_t bh0[4], bh1[4];
            const uint32_t ka0 = kv + kqoff + c * 32;
            const uint32_t ka1 = ka0 + (uint32_t)(16 * (PT * 2));
            ldsm_x4(bh0, ka0);
            ldsm_x4(bh1, ka1);
            mma16816(s[0], qh[c], bh0); mma16816(s[1], qh[c], bh0 + 2);
            mma16816(s[2], qh[c], bh1); mma16816(s[3], qh[c], bh1 + 2);
        }

        // ---- softmax in registers: exp2f (no multiply) ----
        const unsigned w0 = mrow0[it];
        const unsigned w8 = mrow8[it];
#pragma unroll
        for (int j = 0; j < 4; j++) {
            const int bit = j * 8 + tig * 2;
            float p0 = exp2f(s[j][0]);
            float p1 = exp2f(s[j][1]);
            float p2 = exp2f(s[j][2]);
            float p3 = exp2f(s[j][3]);
            p0 = ((w0 >> bit) & 1u)       ? p0 : 0.f;
            p1 = ((w0 >> (bit + 1)) & 1u) ? p1 : 0.f;
            p2 = ((w8 >> bit) & 1u)       ? p2 : 0.f;
            p3 = ((w8 >> (bit + 1)) & 1u) ? p3 : 0.f;
            lsum_g += p0 + p1;
            lsum_8 += p2 + p3;
            s[j][0] = p0; s[j][1] = p1; s[j][2] = p2; s[j][3] = p3;
        }

        // ---- O += P V ----
#pragma unroll
        for (int c2 = 0; c2 < 2; c2++) {
            uint32_t ah[4];
            ah[0] = pack2h(s[2 * c2][0],     s[2 * c2][1]);
            ah[1] = pack2h(s[2 * c2][2],     s[2 * c2][3]);
            ah[2] = pack2h(s[2 * c2 + 1][0], s[2 * c2 + 1][1]);
            ah[3] = pack2h(s[2 * c2 + 1][2], s[2 * c2 + 1][3]);
#pragma unroll
            for (int jp = 0; jp < 4; jp++) {
                uint32_t bh[4];
                const uint32_t va = kv + KV_V + voff +
                                    (uint32_t)(c2 * 16 * (PT * 2)) + jp * 32;
                ldsm_x4_t(bh, va);
                mma16816(o[2 * jp],     ah, bh);
                mma16816(o[2 * jp + 1], ah, bh + 2);
            }
        }
    }

    // ---- epilogue ----
    lsum_g += __shfl_xor_sync(0xffffffffu, lsum_g, 1);
    lsum_g += __shfl_xor_sync(0xffffffffu, lsum_g, 2);
    lsum_8 += __shfl_xor_sync(0xffffffffu, lsum_8, 1);
    lsum_8 += __shfl_xor_sync(0xffffffffu, lsum_8, 2);
    const float inv_g = 1.0f / lsum_g;
    const float inv_8 = 1.0f / lsum_8;

    const size_t d0 = (size_t)(n * S_LEN + qrow_g) * EMB + h * HD;
    const size_t d8 = d0 + (size_t)8 * EMB;
#pragma unroll
    for (int j = 0; j < 8; j++) {
        const int col = j * 8 + tig * 2;
        *(uint32_t*)(g_ao + d0 + col) = pack2h(o[j][0] * inv_g, o[j][1] * inv_g);
        *(uint32_t*)(g_ao + d8 + col) = pack2h(o[j][2] * inv_8, o[j][3] * inv_8);
    }
}

// ---------------------------------------------------------------------------
// Kernel 3: output projection — A and Wo single fp16, BK=32, 2-stage ring
// ---------------------------------------------------------------------------
#define OPKB    80
#define OB2_SZ  20480
#define OB2_B   10240
#define OUT2_SMEM (2 * 20480 + 128)
#define ONIT2 (EMB / 32)

__global__ __launch_bounds__(256, 2)
void out_mma_kernel(const float* __restrict__ bo, float* __restrict__ out)
{
    extern __shared__ char sm[];
    const uint32_t smb = smem_u32(sm);

    const int tid = threadIdx.x, wid = tid >> 5, lane = tid & 31;
    const int r0 = blockIdx.y * 128;
    const int e0 = blockIdx.x * 128;
    const int wr = wid & 3;
    const int wc = wid >> 2;

    const int l7  = lane & 7;
    const int s01 = (lane >> 3) & 1;
    const int s23 = lane >> 4;
    const uint32_t aoff = (uint32_t)((l7 + s01 * 8) * OPKB) + s23 * 16;
    const uint32_t boff = (uint32_t)((s23 * 8 + l7) * OPKB) + s01 * 16;

    float acc[2][8][4];
#pragma unroll
    for (int m = 0; m < 2; m++)
#pragma unroll
        for (int j = 0; j < 8; j++)
#pragma unroll
            for (int u = 0; u < 4; u++) acc[m][j][u] = 0.f;

    const int ar0 = tid >> 2,          aq0 = tid & 3;
    const int ar1 = (tid + 256) >> 2,  aq1 = tid & 3;
    const uint32_t os0 = (uint32_t)(ar0 * OPKB + aq0 * 16);
    const uint32_t os1 = (uint32_t)(ar1 * OPKB + aq1 * 16);
    const size_t ag0 = (size_t)(r0 + ar0) * EMB + aq0 * 8;
    const size_t ag1 = (size_t)(r0 + ar1) * EMB + aq1 * 8;
    const size_t bg0 = (size_t)(e0 + ar0) * EMB + aq0 * 8;
    const size_t bg1 = (size_t)(e0 + ar1) * EMB + aq1 * 8;

    {
        const uint32_t d = smb;
        cp16(d + os0,         g_ao + ag0);  cp16(d + os1,         g_ao + ag1);
        cp16(d + OB2_B + os0, g_wo + bg0);  cp16(d + OB2_B + os1, g_wo + bg1);
    }
    CP_COMMIT();

    for (int ic = 0; ic < ONIT2; ic++) {
        const uint32_t buf = smb + (ic & 1) * OB2_SZ;

        CP_WAIT0();
        __syncthreads();

        if (ic + 1 < ONIT2) {
            const int c1 = (ic + 1) * 32;
            const uint32_t d = smb + ((ic + 1) & 1) * OB2_SZ;
            cp16(d + os0,         g_ao + ag0 + c1);  cp16(d + os1,         g_ao + ag1 + c1);
            cp16(d + OB2_B + os0, g_wo + bg0 + c1);  cp16(d + OB2_B + os1, g_wo + bg1 + c1);
        }
        CP_COMMIT();

#pragma unroll
        for (int kk = 0; kk < 2; kk++) {
            uint32_t ah0[4], ah1[4];
            const uint32_t aa0 = buf + (uint32_t)(wr * 32 * OPKB) + aoff + kk * 32;
            const uint32_t aa1 = aa0 + (uint32_t)(16 * OPKB);
            ldsm_x4(ah0, aa0);
            ldsm_x4(ah1, aa1);
#pragma unroll
            for (int jj = 0; jj < 4; jj++) {
                uint32_t bh[4];
                const uint32_t ba = buf + OB2_B +
                    (uint32_t)((wc * 64 + jj * 16) * OPKB) + boff + kk * 32;
                ldsm_x4(bh, ba);
                mma16816(acc[0][2 * jj],     ah0, bh); mma16816(acc[0][2 * jj + 1], ah0, bh + 2);
                mma16816(acc[1][2 * jj],     ah1, bh); mma16816(acc[1][2 * jj + 1], ah1, bh + 2);
            }
        }
    }

    const int g   = lane >> 2;
    const int tig = lane & 3;
#pragma unroll
    for (int m = 0; m < 2; m++) {
        const int row  = r0 + wr * 32 + m * 16 + g;
        const int row8 = row + 8;
#pragma unroll
        for (int jn = 0; jn < 8; jn++) {
            const int col = e0 + wc * 64 + jn * 8 + tig * 2;
            const float2 bb = *(const float2*)(bo + col);
            float2 v0 = make_float2(acc[m][jn][0] + bb.x, acc[m][jn][1] + bb.y);
            float2 v1 = make_float2(acc[m][jn][2] + bb.x, acc[m][jn][3] + bb.y);
            *(float2*)(out + (size_t)row  * EMB + col) = v0;
            *(float2*)(out + (size_t)row8 * EMB + col) = v1;
        }
    }
}

// ---------------------------------------------------------------------------
extern "C" void kernel_launch(void* const* d_in, const int* in_sizes, int n_in,
                              void* d_out, int out_size)
{
    const float* values  = (const float*)d_in[0];
    const float* queries = (const float*)d_in[1];
    const float* keys    = (const float*)d_in[2];
    const int*   mask    = (const int*)  d_in[3];
    const float* Wv      = (const float*)d_in[4];
    const float* Wk      = (const float*)d_in[5];
    const float* Wq      = (const float*)d_in[6];
    const float* Wo      = (const float*)d_in[7];
    const float* bo      = (const float*)d_in[8];
    float* out = (float*)d_out;

    static bool attr_set = false;
    if (!attr_set) {
        cudaFuncSetAttribute(proj_wmma_kernel,
                             cudaFuncAttributeMaxDynamicSharedMemorySize, PJ_SMEM);
        cudaFuncSetAttribute(attn_mma_kernel,
                             cudaFuncAttributeMaxDynamicSharedMemorySize, ATTN_SMEM);
        cudaFuncSetAttribute(out_mma_kernel,
                             cudaFuncAttributeMaxDynamicSharedMemorySize, OUT2_SMEM);
        attr_set = true;
    }

    mask_pack_kernel<<<(N_B * S_LEN * MWORDS * 32) / 256, 256>>>(mask);
    wo_half_kernel<<<(EMB * EMB) / (256 * 8), 256>>>(Wo);

    dim3 pgrid(S_LEN / 128, N_B * HEADS, 3);
    proj_wmma_kernel<<<pgrid, 256, PJ_SMEM>>>(queries, keys, values, Wq, Wk, Wv);

    dim3 agrid(HEADS, S_LEN / 128, N_B);
    attn_mma_kernel<<<agrid, 256, ATTN_SMEM>>>();

    dim3 ggrid(EMB / 128, (N_B * S_LEN) / 128);
    out_mma_kernel<<<ggrid, 256, OUT2_SMEM>>>(bo, out);
}

// round 16
// speedup vs baseline: 1.1904x; 1.0045x over previous
#include <cuda_runtime.h>
#include <cuda_fp16.h>
#include <mma.h>
#include <cstdint>

using namespace nvcuda;

#define N_B    4
#define S_LEN  2048
#define EMB    1024
#define HEADS  16
#define HD     64
#define MWORDS (S_LEN / 32)

#define PT   72    // fp16 smem pitch (144 B rows)

// ---------------- scratch (device globals) ---------------------------------
__device__ __half g_q[N_B * HEADS * S_LEN * HD];    // fp16, pre-scaled log2(e)/32
__device__ __half g_k[N_B * HEADS * S_LEN * HD];
__device__ __half g_v[N_B * HEADS * S_LEN * HD];
__device__ __half g_ao[N_B * S_LEN * EMB];
__device__ __half g_wo[EMB * EMB];
__device__ unsigned g_mbits[N_B * S_LEN * MWORDS];

__device__ __forceinline__ uint32_t pack2h(float a, float b) {
    __half2 h = __floats2half2_rn(a, b);
    return *reinterpret_cast<uint32_t*>(&h);
}

__device__ __forceinline__ uint32_t smem_u32(const void* p) {
    uint32_t a;
    asm("{ .reg .u64 t; cvta.to.shared.u64 t, %1; cvt.u32.u64 %0, t; }"
        : "=r"(a) : "l"(p));
    return a;
}

// ---- tensor-core / async-copy primitives ----------------------------------
__device__ __forceinline__ void ldsm_x4(uint32_t* r, uint32_t addr) {
    asm volatile("ldmatrix.sync.aligned.m8n8.x4.shared.b16 {%0,%1,%2,%3}, [%4];"
                 : "=r"(r[0]), "=r"(r[1]), "=r"(r[2]), "=r"(r[3]) : "r"(addr));
}
__device__ __forceinline__ void ldsm_x4_t(uint32_t* r, uint32_t addr) {
    asm volatile("ldmatrix.sync.aligned.m8n8.x4.trans.shared.b16 {%0,%1,%2,%3}, [%4];"
                 : "=r"(r[0]), "=r"(r[1]), "=r"(r[2]), "=r"(r[3]) : "r"(addr));
}
__device__ __forceinline__ void mma16816(float* d, const uint32_t* a, const uint32_t* b) {
    asm volatile(
        "mma.sync.aligned.m16n8k16.row.col.f32.f16.f16.f32 "
        "{%0,%1,%2,%3}, {%4,%5,%6,%7}, {%8,%9}, {%0,%1,%2,%3};"
        : "+f"(d[0]), "+f"(d[1]), "+f"(d[2]), "+f"(d[3])
        : "r"(a[0]), "r"(a[1]), "r"(a[2]), "r"(a[3]), "r"(b[0]), "r"(b[1]));
}
__device__ __forceinline__ void cp16(uint32_t dst, const void* src) {
    asm volatile("cp.async.cg.shared.global [%0], [%1], 16;" :: "r"(dst), "l"(src));
}
#define CP_COMMIT() asm volatile("cp.async.commit_group;" ::: "memory")
#define CP_WAIT0()  asm volatile("cp.async.wait_group 0;" ::: "memory")
#define CP_WAIT1()  asm volatile("cp.async.wait_group 1;" ::: "memory")

// stage nrows x 64 f32 -> SINGLE fp16 smem pitch PT
__device__ __forceinline__ void stage_rows_f32_single(const float* __restrict__ src,
                                                      size_t stride, char* s_x, int t)
{
    const int r    = t >> 1;
    const int half = t & 1;
    const float4* s4 = (const float4*)(src + (size_t)r * stride) + half * 8;
#pragma unroll
    for (int tt = 0; tt < 4; tt++) {
        float4 a = s4[2 * tt], b = s4[2 * tt + 1];
        uint32_t H[4];
        H[0] = pack2h(a.x, a.y); H[1] = pack2h(a.z, a.w);
        H[2] = pack2h(b.x, b.y); H[3] = pack2h(b.z, b.w);
        uint32_t off = (uint32_t)(r * (PT * 2) + half * 64 + tt * 16);
        *(uint4*)(s_x + off) = make_uint4(H[0], H[1], H[2], H[3]);
    }
}

// ---------------------------------------------------------------------------
// Kernel 0a: pack mask bits
// ---------------------------------------------------------------------------
__global__ __launch_bounds__(256)
void mask_pack_kernel(const int* __restrict__ mask)
{
    int gid  = blockIdx.x * 256 + threadIdx.x;
    int w    = gid >> 5;
    int lane = gid & 31;
    int v = mask[(size_t)w * 32 + lane];
    unsigned bits = __ballot_sync(0xffffffffu, v != 0);
    if (lane == 0) g_mbits[w] = bits;
}

// ---------------------------------------------------------------------------
// Kernel 0b: convert Wo to single fp16
// ---------------------------------------------------------------------------
__global__ __launch_bounds__(256)
void wo_half_kernel(const float* __restrict__ Wo)
{
    size_t idx = ((size_t)blockIdx.x * 256 + threadIdx.x) * 8;
    float4 a = *(const float4*)(Wo + idx);
    float4 b = *(const float4*)(Wo + idx + 4);
    uint32_t H[4];
    H[0] = pack2h(a.x, a.y); H[1] = pack2h(a.z, a.w);
    H[2] = pack2h(b.x, b.y); H[3] = pack2h(b.z, b.w);
    *(uint4*)(g_wo + idx) = make_uint4(H[0], H[1], H[2], H[3]);
}

// ---------------------------------------------------------------------------
// Kernel 1: projections — raw mma.sync, direct packed stores (no scr smem)
// grid (S/128, N_B*HEADS, 3), 256 threads; warp = 16 rows x 64 cols
// ---------------------------------------------------------------------------
#define PJ_W   0
#define PJ_X   9216
#define PJ_SMEM (9216 + 18432)

__global__ __launch_bounds__(256, 2)
void proj_mma_kernel(const float* __restrict__ xq, const float* __restrict__ xk,
                     const float* __restrict__ xv,
                     const float* __restrict__ Wq, const float* __restrict__ Wk,
                     const float* __restrict__ Wv)
{
    extern __shared__ char sm[];
    const uint32_t smb = smem_u32(sm);

    const int which = blockIdx.z;
    const float* X; const float* W; __half* Y;
    if (which == 0)      { X = xq; W = Wq; Y = g_q; }
    else if (which == 1) { X = xk; W = Wk; Y = g_k; }
    else                 { X = xv; W = Wv; Y = g_v; }
    const float oscale = (which == 0) ? (1.4426950408889634f * 0.03125f) : 1.0f;

    const int nh = blockIdx.y;
    const int n  = nh / HEADS;
    const int h  = nh % HEADS;
    const int s0 = blockIdx.x * 128;
    const int tid = threadIdx.x, wid = tid >> 5, lane = tid & 31;

    stage_rows_f32_single(X + (size_t)(n * S_LEN + s0) * EMB + h * HD, EMB,
                          sm + PJ_X, tid);
    if (tid < 128)
        stage_rows_f32_single(W, HD, sm + PJ_W, tid);
    __syncthreads();

    const int l7  = lane & 7;
    const int s01 = (lane >> 3) & 1;
    const int s23 = (lane >> 4) & 1;

    // A fragments: X rows wid*16..+15
    uint32_t ax[4][4];
    {
        uint32_t base = smb + PJ_X +
                        (uint32_t)((wid * 16 + l7 + s01 * 8) * (PT * 2)) + s23 * 16;
#pragma unroll
        for (int c = 0; c < 4; c++)
            ldsm_x4(ax[c], base + c * 32);
    }

    // B: W (col-major usage), 64 cols = 4 x4 loads per c-chunk
    const uint32_t kboff = (uint32_t)(((lane >> 4) * 8 + l7) * (PT * 2)) + ((lane >> 3) & 1) * 16;

    float acc[8][4];
#pragma unroll
    for (int j = 0; j < 8; j++)
#pragma unroll
        for (int u = 0; u < 4; u++) acc[j][u] = 0.f;

#pragma unroll
    for (int c = 0; c < 4; c++) {
#pragma unroll
        for (int jp = 0; jp < 4; jp++) {
            uint32_t bh[4];
            ldsm_x4(bh, smb + PJ_W + kboff + (uint32_t)(jp * 16 * (PT * 2)) + c * 32);
            mma16816(acc[2 * jp],     ax[c], bh);
            mma16816(acc[2 * jp + 1], ax[c], bh + 2);
        }
    }

    // epilogue: direct packed fp16 stores
    const int g   = lane >> 2;
    const int tig = lane & 3;
    const size_t yb = (size_t)((n * HEADS + h) * S_LEN + s0 + wid * 16 + g) * HD;
    const size_t yb8 = yb + (size_t)8 * HD;
#pragma unroll
    for (int j = 0; j < 8; j++) {
        const int col = j * 8 + tig * 2;
        *(uint32_t*)(Y + yb  + col) = pack2h(acc[j][0] * oscale, acc[j][1] * oscale);
        *(uint32_t*)(Y + yb8 + col) = pack2h(acc[j][2] * oscale, acc[j][3] * oscale);
    }
}

// ---------------------------------------------------------------------------
// Kernel 2: flash attention — UNCHANGED from R15 (measured 217us)
// ---------------------------------------------------------------------------
#define A_Q    0
#define A_KV0  18432
#define A_KV1  27648
#define KV_V   4608
#define ATTN_SMEM (36864 + 256)
#define NIT (S_LEN / 32)

__global__ __launch_bounds__(256, 2)
void attn_mma_kernel()
{
    extern __shared__ char sm[];
    const int tid = threadIdx.x, wid = tid >> 5, lane = tid & 31;
    const int h = blockIdx.x, qt = blockIdx.y, n = blockIdx.z;
    const int q0 = qt * 128;

    const size_t head_base = (size_t)(n * HEADS + h) * S_LEN * HD;
    const __half* Q = g_q + head_base + (size_t)q0 * HD;
    const __half* K = g_k + head_base;
    const __half* V = g_v + head_base;

    const uint32_t smb = smem_u32(sm);

    const int str = tid >> 3, soct = tid & 7;
    const uint32_t soff = (uint32_t)(str * (PT * 2) + soct * 16);
    {
        const size_t gsrc = (size_t)str * HD + soct * 8;
        cp16(smb + A_KV0 + soff,        K + gsrc);
        cp16(smb + A_KV0 + KV_V + soff, V + gsrc);
    }
    CP_COMMIT();

    {
        const int r = tid >> 1, half = tid & 1;
        const char* sq = (const char*)(Q + (size_t)r * HD + half * 32);
        uint32_t off = (uint32_t)(r * (PT * 2) + half * 64);
#pragma unroll
        for (int tt = 0; tt < 4; tt++)
            *(uint4*)(sm + A_Q + off + tt * 16) = *(const uint4*)(sq + tt * 16);
    }
    __syncthreads();

    const int l7  = lane & 7;
    const int s01 = (lane >> 3) & 1;
    const int s23 = (lane >> 4) & 1;

    uint32_t qh[4][4];
    {
        uint32_t base = smb + (uint32_t)((wid * 16 + l7 + s01 * 8) * (PT * 2)) + s23 * 16;
#pragma unroll
        for (int c = 0; c < 4; c++)
            ldsm_x4(qh[c], base + A_Q + c * 32);
    }

    const int g   = lane >> 2;
    const int tig = lane & 3;
    const int qrow_g  = q0 + wid * 16 + g;
    const unsigned* mrow0 = g_mbits + (size_t)(n * S_LEN + qrow_g) * MWORDS;
    const unsigned* mrow8 = mrow0 + 8 * MWORDS;

    const uint32_t kqoff = (uint32_t)(((lane >> 4) * 8 + l7) * (PT * 2)) + ((lane >> 3) & 1) * 16;
    const uint32_t voff  = (uint32_t)((((lane >> 3) & 1) * 8 + l7) * (PT * 2)) + (lane >> 4) * 16;

    float o[8][4];
#pragma unroll
    for (int j = 0; j < 8; j++)
#pragma unroll
        for (int u = 0; u < 4; u++) o[j][u] = 0.f;
    float lsum_g = 0.f, lsum_8 = 0.f;

    for (int it = 0; it < NIT; it++) {
        const uint32_t kv = smb + ((it & 1) ? A_KV1 : A_KV0);

        CP_WAIT0();
        __syncthreads();

        if (it + 1 < NIT) {
            const size_t gsrc = (size_t)((it + 1) * 32 + str) * HD + soct * 8;
            const uint32_t d = smb + (((it + 1) & 1) ? A_KV1 : A_KV0);
            cp16(d + soff,        K + gsrc);
            cp16(d + KV_V + soff, V + gsrc);
        }
        CP_COMMIT();

        float s[4][4];
#pragma unroll
        for (int j = 0; j < 4; j++)
#pragma unroll
            for (int u = 0; u < 4; u++) s[j][u] = 0.f;

#pragma unroll
        for (int c = 0; c < 4; c++) {
            uint32_t bh0[4], bh1[4];
            const uint32_t ka0 = kv + kqoff + c * 32;
            const uint32_t ka1 = ka0 + (uint32_t)(16 * (PT * 2));
            ldsm_x4(bh0, ka0);
            ldsm_x4(bh1, ka1);
            mma16816(s[0], qh[c], bh0); mma16816(s[1], qh[c], bh0 + 2);
            mma16816(s[2], qh[c], bh1); mma16816(s[3], qh[c], bh1 + 2);
        }

        const unsigned w0 = mrow0[it];
        const unsigned w8 = mrow8[it];
#pragma unroll
        for (int j = 0; j < 4; j++) {
            const int bit = j * 8 + tig * 2;
            float p0 = exp2f(s[j][0]);
            float p1 = exp2f(s[j][1]);
            float p2 = exp2f(s[j][2]);
            float p3 = exp2f(s[j][3]);
            p0 = ((w0 >> bit) & 1u)       ? p0 : 0.f;
            p1 = ((w0 >> (bit + 1)) & 1u) ? p1 : 0.f;
            p2 = ((w8 >> bit) & 1u)       ? p2 : 0.f;
            p3 = ((w8 >> (bit + 1)) & 1u) ? p3 : 0.f;
            lsum_g += p0 + p1;
            lsum_8 += p2 + p3;
            s[j][0] = p0; s[j][1] = p1; s[j][2] = p2; s[j][3] = p3;
        }

#pragma unroll
        for (int c2 = 0; c2 < 2; c2++) {
            uint32_t ah[4];
            ah[0] = pack2h(s[2 * c2][0],     s[2 * c2][1]);
            ah[1] = pack2h(s[2 * c2][2],     s[2 * c2][3]);
            ah[2] = pack2h(s[2 * c2 + 1][0], s[2 * c2 + 1][1]);
            ah[3] = pack2h(s[2 * c2 + 1][2], s[2 * c2 + 1][3]);
#pragma unroll
            for (int jp = 0; jp < 4; jp++) {
                uint32_t bh[4];
                const uint32_t va = kv + KV_V + voff +
                                    (uint32_t)(c2 * 16 * (PT * 2)) + jp * 32;
                ldsm_x4_t(bh, va);
                mma16816(o[2 * jp],     ah, bh);
                mma16816(o[2 * jp + 1], ah, bh + 2);
            }
        }
    }

    lsum_g += __shfl_xor_sync(0xffffffffu, lsum_g, 1);
    lsum_g += __shfl_xor_sync(0xffffffffu, lsum_g, 2);
    lsum_8 += __shfl_xor_sync(0xffffffffu, lsum_8, 1);
    lsum_8 += __shfl_xor_sync(0xffffffffu, lsum_8, 2);
    const float inv_g = 1.0f / lsum_g;
    const float inv_8 = 1.0f / lsum_8;

    const size_t d0 = (size_t)(n * S_LEN + qrow_g) * EMB + h * HD;
    const size_t d8 = d0 + (size_t)8 * EMB;
#pragma unroll
    for (int j = 0; j < 8; j++) {
        const int col = j * 8 + tig * 2;
        *(uint32_t*)(g_ao + d0 + col) = pack2h(o[j][0] * inv_g, o[j][1] * inv_g);
        *(uint32_t*)(g_ao + d8 + col) = pack2h(o[j][2] * inv_8, o[j][3] * inv_8);
    }
}

// ---------------------------------------------------------------------------
// Kernel 3: output projection — 3-stage cp.async ring with wait_group 1
// ---------------------------------------------------------------------------
#define OPKB    80
#define OB2_SZ  20480
#define OB2_B   10240
#define OUT2_SMEM (3 * 20480 + 128)
#define ONIT2 (EMB / 32)

__global__ __launch_bounds__(256, 2)
void out_mma_kernel(const float* __restrict__ bo, float* __restrict__ out)
{
    extern __shared__ char sm[];
    const uint32_t smb = smem_u32(sm);

    const int tid = threadIdx.x, wid = tid >> 5, lane = tid & 31;
    const int r0 = blockIdx.y * 128;
    const int e0 = blockIdx.x * 128;
    const int wr = wid & 3;
    const int wc = wid >> 2;

    const int l7  = lane & 7;
    const int s01 = (lane >> 3) & 1;
    const int s23 = lane >> 4;
    const uint32_t aoff = (uint32_t)((l7 + s01 * 8) * OPKB) + s23 * 16;
    const uint32_t boff = (uint32_t)((s23 * 8 + l7) * OPKB) + s01 * 16;

    float acc[2][8][4];
#pragma unroll
    for (int m = 0; m < 2; m++)
#pragma unroll
        for (int j = 0; j < 8; j++)
#pragma unroll
            for (int u = 0; u < 4; u++) acc[m][j][u] = 0.f;

    const int ar0 = tid >> 2,          aq0 = tid & 3;
    const int ar1 = (tid + 256) >> 2,  aq1 = tid & 3;
    const uint32_t os0 = (uint32_t)(ar0 * OPKB + aq0 * 16);
    const uint32_t os1 = (uint32_t)(ar1 * OPKB + aq1 * 16);
    const size_t ag0 = (size_t)(r0 + ar0) * EMB + aq0 * 8;
    const size_t ag1 = (size_t)(r0 + ar1) * EMB + aq1 * 8;
    const size_t bg0 = (size_t)(e0 + ar0) * EMB + aq0 * 8;
    const size_t bg1 = (size_t)(e0 + ar1) * EMB + aq1 * 8;

    // prologue: prefetch k-chunks 0 and 1
#pragma unroll
    for (int pt = 0; pt < 2; pt++) {
        const uint32_t d = smb + pt * OB2_SZ;
        cp16(d + os0,         g_ao + ag0 + pt * 32);  cp16(d + os1,         g_ao + ag1 + pt * 32);
        cp16(d + OB2_B + os0, g_wo + bg0 + pt * 32);  cp16(d + OB2_B + os1, g_wo + bg1 + pt * 32);
        CP_COMMIT();
    }

    for (int ic = 0; ic < ONIT2; ic++) {
        const uint32_t buf = smb + (ic % 3) * OB2_SZ;

        CP_WAIT1();
        __syncthreads();

        if (ic + 2 < ONIT2) {
            const int c1 = (ic + 2) * 32;
            const uint32_t d = smb + ((ic + 2) % 3) * OB2_SZ;
            cp16(d + os0,         g_ao + ag0 + c1);  cp16(d + os1,         g_ao + ag1 + c1);
            cp16(d + OB2_B + os0, g_wo + bg0 + c1);  cp16(d + OB2_B + os1, g_wo + bg1 + c1);
        }
        CP_COMMIT();

#pragma unroll
        for (int kk = 0; kk < 2; kk++) {
            uint32_t ah0[4], ah1[4];
            const uint32_t aa0 = buf + (uint32_t)(wr * 32 * OPKB) + aoff + kk * 32;
            const uint32_t aa1 = aa0 + (uint32_t)(16 * OPKB);
            ldsm_x4(ah0, aa0);
            ldsm_x4(ah1, aa1);
#pragma unroll
            for (int jj = 0; jj < 4; jj++) {
                uint32_t bh[4];
                const uint32_t ba = buf + OB2_B +
                    (uint32_t)((wc * 64 + jj * 16) * OPKB) + boff + kk * 32;
                ldsm_x4(bh, ba);
                mma16816(acc[0][2 * jj],     ah0, bh); mma16816(acc[0][2 * jj + 1], ah0, bh + 2);
                mma16816(acc[1][2 * jj],     ah1, bh); mma16816(acc[1][2 * jj + 1], ah1, bh + 2);
            }
        }
    }

    const int g   = lane >> 2;
    const int tig = lane & 3;
#pragma unroll
    for (int m = 0; m < 2; m++) {
        const int row  = r0 + wr * 32 + m * 16 + g;
        const int row8 = row + 8;
#pragma unroll
        for (int jn = 0; jn < 8; jn++) {
            const int col = e0 + wc * 64 + jn * 8 + tig * 2;
            const float2 bb = *(const float2*)(bo + col);
            float2 v0 = make_float2(acc[m][jn][0] + bb.x, acc[m][jn][1] + bb.y);
            float2 v1 = make_float2(acc[m][jn][2] + bb.x, acc[m][jn][3] + bb.y);
            *(float2*)(out + (size_t)row  * EMB + col) = v0;
            *(float2*)(out + (size_t)row8 * EMB + col) = v1;
        }
    }
}

// ---------------------------------------------------------------------------
extern "C" void kernel_launch(void* const* d_in, const int* in_sizes, int n_in,
                              void* d_out, int out_size)
{
    const float* values  = (const float*)d_in[0];
    const float* queries = (const float*)d_in[1];
    const float* keys    = (const float*)d_in[2];
    const int*   mask    = (const int*)  d_in[3];
    const float* Wv      = (const float*)d_in[4];
    const float* Wk      = (const float*)d_in[5];
    const float* Wq      = (const float*)d_in[6];
    const float* Wo      = (const float*)d_in[7];
    const float* bo      = (const float*)d_in[8];
    float* out = (float*)d_out;

    static bool attr_set = false;
    if (!attr_set) {
        cudaFuncSetAttribute(proj_mma_kernel,
                             cudaFuncAttributeMaxDynamicSharedMemorySize, PJ_SMEM);
        cudaFuncSetAttribute(attn_mma_kernel,
                             cudaFuncAttributeMaxDynamicSharedMemorySize, ATTN_SMEM);
        cudaFuncSetAttribute(out_mma_kernel,
                             cudaFuncAttributeMaxDynamicSharedMemorySize, OUT2_SMEM);
        attr_set = true;
    }

    mask_pack_kernel<<<(N_B * S_LEN * MWORDS * 32) / 256, 256>>>(mask);
    wo_half_kernel<<<(EMB * EMB) / (256 * 8), 256>>>(Wo);

    dim3 pgrid(S_LEN / 128, N_B * HEADS, 3);
    proj_mma_kernel<<<pgrid, 256, PJ_SMEM>>>(queries, keys, values, Wq, Wk, Wv);

    dim3 agrid(HEADS, S_LEN / 128, N_B);
    attn_mma_kernel<<<agrid, 256, ATTN_SMEM>>>();

    dim3 ggrid(EMB / 128, (N_B * S_LEN) / 128);
    out_mma_kernel<<<ggrid, 256, OUT2_SMEM>>>(bo, out);
}